// round 3
// baseline (speedup 1.0000x reference)
#include <cuda_runtime.h>
#include <cstdint>

#define D 128
#define MAXN 100000
#define MAXE 600000
#define NEG_SLOPE 0.01f
#define FULL 0xFFFFFFFFu

// ---------------- scratch (static device globals; no allocation) ----------------
static __device__ float g_vl[3][D];
static __device__ float g_vr[3][D];
static __device__ float g_M[D * D];            // Wq^T @ Wk
static __device__ float g_sl[3][MAXN];
static __device__ float g_sr[3][MAXN];
static __device__ int   g_cnt[3][MAXN];
static __device__ int   g_cur[3][MAXN];
static __device__ int   g_off[3][MAXN + 1];
static __device__ int2  g_epack[3][MAXE];      // (src, exp-score bits), sorted by dst

// ---------------- K0a: v_l / v_r vectors ----------------
__global__ void k_vec(const float* __restrict__ W1_0, const float* __restrict__ W1_1,
                      const float* __restrict__ W1_2, const float* __restrict__ w2_0,
                      const float* __restrict__ w2_1, const float* __restrict__ w2_2) {
    int r = blockIdx.x >> 1;
    int half = blockIdx.x & 1;
    const float* W1 = (r == 0) ? W1_0 : (r == 1) ? W1_1 : W1_2;
    const float* w2 = ((r == 0) ? w2_0 : (r == 1) ? w2_1 : w2_2) + half * D;
    int j = threadIdx.x;
    float s = 0.f;
#pragma unroll 8
    for (int i = 0; i < D; i++) s += W1[i * D + j] * w2[i];
    if (half) g_vr[r][j] = s; else g_vl[r][j] = s;
}

// ---------------- K0b: M = Wq^T @ Wk ----------------
__global__ void k_M(const float* __restrict__ Wq, const float* __restrict__ Wk) {
    int dd = blockIdx.x;
    int j = threadIdx.x;
    float s = 0.f;
#pragma unroll 8
    for (int e = 0; e < D; e++) s += Wq[e * D + dd] * Wk[e * D + j];
    g_M[dd * D + j] = s;
}

// ---------------- K1: zero counts + cursors ----------------
__global__ void k_zero() {
    int i = blockIdx.x * blockDim.x + threadIdx.x;
    int tot = 3 * MAXN;
    int stride = gridDim.x * blockDim.x;
    for (; i < tot; i += stride) {
        (&g_cnt[0][0])[i] = 0;
        (&g_cur[0][0])[i] = 0;
    }
}

// ---------------- K2: per-node scores, warp per 8 nodes ----------------
__global__ void k_scores(const float* __restrict__ Nmat, int n) {
    int w = (blockIdx.x * blockDim.x + threadIdx.x) >> 5;
    int lane = threadIdx.x & 31;
    int node0 = w * 8;
    if (node0 >= n) return;
    const float4* N4 = (const float4*)Nmat;
    float4 a0 = ((const float4*)g_vl[0])[lane];
    float4 b0 = ((const float4*)g_vr[0])[lane];
    float4 a1 = ((const float4*)g_vl[1])[lane];
    float4 b1 = ((const float4*)g_vr[1])[lane];
    float4 a2 = ((const float4*)g_vl[2])[lane];
    float4 b2 = ((const float4*)g_vr[2])[lane];
#pragma unroll
    for (int q = 0; q < 8; q++) {
        int node = node0 + q;
        if (node >= n) break;
        float4 x = N4[(size_t)node * 32 + lane];
        float p0 = x.x * a0.x + x.y * a0.y + x.z * a0.z + x.w * a0.w;
        float p1 = x.x * b0.x + x.y * b0.y + x.z * b0.z + x.w * b0.w;
        float p2 = x.x * a1.x + x.y * a1.y + x.z * a1.z + x.w * a1.w;
        float p3 = x.x * b1.x + x.y * b1.y + x.z * b1.z + x.w * b1.w;
        float p4 = x.x * a2.x + x.y * a2.y + x.z * a2.z + x.w * a2.w;
        float p5 = x.x * b2.x + x.y * b2.y + x.z * b2.z + x.w * b2.w;
#pragma unroll
        for (int o = 16; o; o >>= 1) {
            p0 += __shfl_xor_sync(FULL, p0, o);
            p1 += __shfl_xor_sync(FULL, p1, o);
            p2 += __shfl_xor_sync(FULL, p2, o);
            p3 += __shfl_xor_sync(FULL, p3, o);
            p4 += __shfl_xor_sync(FULL, p4, o);
            p5 += __shfl_xor_sync(FULL, p5, o);
        }
        if (lane == 0) {
            g_sl[0][node] = p0; g_sr[0][node] = p1;
            g_sl[1][node] = p2; g_sr[1][node] = p3;
            g_sl[2][node] = p4; g_sr[2][node] = p5;
        }
    }
}

// ---------------- K3: in-degree counts (all 3 relations, grid.y = r) ----------------
__global__ void k_count(const int* __restrict__ d0, const int* __restrict__ d1,
                        const int* __restrict__ d2, int e0, int e1, int e2) {
    int r = blockIdx.y;
    const int* dst = (r == 0) ? d0 : (r == 1) ? d1 : d2;
    int E = (r == 0) ? e0 : (r == 1) ? e1 : e2;
    int t = blockIdx.x * blockDim.x + threadIdx.x;
    if (t >= E) return;
    atomicAdd(&g_cnt[r][dst[t]], 1);
}

// ---------------- K4: exclusive scan -> CSR offsets (1 block per relation) ----------------
__global__ void k_scan(int n) {
    int r = blockIdx.x;
    __shared__ int warpsum[32];
    int tid = threadIdx.x;
    int lane = tid & 31, wid = tid >> 5;
    int chunk = (n + 1023) >> 10;
    int beg = tid * chunk;
    int end = beg + chunk; if (end > n) end = n;
    if (beg > n) beg = n;
    int loc = 0;
    for (int i = beg; i < end; i++) loc += g_cnt[r][i];
    int v = loc;
#pragma unroll
    for (int o = 1; o < 32; o <<= 1) {
        int t = __shfl_up_sync(FULL, v, o);
        if (lane >= o) v += t;
    }
    if (lane == 31) warpsum[wid] = v;
    __syncthreads();
    if (wid == 0) {
        int s = warpsum[lane];
#pragma unroll
        for (int o = 1; o < 32; o <<= 1) {
            int t = __shfl_up_sync(FULL, s, o);
            if (lane >= o) s += t;
        }
        warpsum[lane] = s;
    }
    __syncthreads();
    int excl = v - loc + (wid ? warpsum[wid - 1] : 0);
    int run = excl;
    for (int i = beg; i < end; i++) {
        g_off[r][i] = run;
        run += g_cnt[r][i];
    }
    if (end == n) g_off[r][n] = run;
}

// ---------------- K5: scatter edges into CSR order with exp-score ----------------
__global__ void k_scatter(const int* __restrict__ s0, const int* __restrict__ s1,
                          const int* __restrict__ s2, const int* __restrict__ d0,
                          const int* __restrict__ d1, const int* __restrict__ d2,
                          int e0, int e1, int e2) {
    int r = blockIdx.y;
    const int* src = (r == 0) ? s0 : (r == 1) ? s1 : s2;
    const int* dst = (r == 0) ? d0 : (r == 1) ? d1 : d2;
    int E = (r == 0) ? e0 : (r == 1) ? e1 : e2;
    int t = blockIdx.x * blockDim.x + threadIdx.x;
    if (t >= E) return;
    int s = src[t];
    int d = dst[t];
    float ev = g_sl[r][s] + g_sr[r][d];
    ev = (ev >= 0.f) ? ev : NEG_SLOPE * ev;
    float ex = __expf(ev);
    int pos = g_off[r][d] + atomicAdd(&g_cur[r][d], 1);
    g_epack[r][pos] = make_int2(s, __float_as_int(ex));
}

// ---------------- K6: fused aggregation + attention, warp per 4 nodes ----------------
__global__ void __launch_bounds__(256)
k_agg(const float* __restrict__ Nmat, float* __restrict__ out,
      int n, const int* __restrict__ tptr) {
    int w = (blockIdx.x * blockDim.x + threadIdx.x) >> 5;
    int lane = threadIdx.x & 31;
    int node0 = w * 4;
    if (node0 >= n) return;

    const float4* N4 = (const float4*)Nmat;
    float4 hv[4][3];

    // ---- Phase A: aggregation (h[q][r] in registers) ----
#pragma unroll
    for (int q = 0; q < 4; q++) {
        int node = node0 + q;
#pragma unroll
        for (int r = 0; r < 3; r++) {
            float4 acc = make_float4(0.f, 0.f, 0.f, 0.f);
            float den = 0.f;
            if (node < n) {
                int beg = g_off[r][node];
                int end = g_off[r][node + 1];
                const int2* ep = g_epack[r];
                for (int base = beg; base < end; base += 32) {
                    int cnt = end - base; if (cnt > 32) cnt = 32;
                    int2 evp = make_int2(0, 0);
                    if (lane < cnt) evp = ep[base + lane];
#pragma unroll 4
                    for (int j = 0; j < cnt; j++) {
                        int s = __shfl_sync(FULL, evp.x, j);
                        float ex = __int_as_float(__shfl_sync(FULL, evp.y, j));
                        float4 nv = N4[(size_t)s * 32 + lane];
                        acc.x += ex * nv.x; acc.y += ex * nv.y;
                        acc.z += ex * nv.z; acc.w += ex * nv.w;
                        den += ex;
                    }
                }
            }
            float iv = (den > 0.f) ? (1.f / den) : 0.f;
            hv[q][r] = make_float4(acc.x * iv, acc.y * iv, acc.z * iv, acc.w * iv);
        }
    }

    // ---- select target h ----
    int t = tptr ? tptr[0] : 0;
    t = (t < 0) ? 0 : ((t > 2) ? 2 : t);
    float4 ht[4];
#pragma unroll
    for (int q = 0; q < 4; q++)
        ht[q] = (t == 0) ? hv[q][0] : ((t == 1) ? hv[q][1] : hv[q][2]);

    // ---- Phase B: u[q] = ht[q] @ M, sharing M row loads across 4 nodes ----
    float4 u[4];
#pragma unroll
    for (int q = 0; q < 4; q++) u[q] = make_float4(0.f, 0.f, 0.f, 0.f);
    const float4* M4 = (const float4*)g_M;
#pragma unroll 4
    for (int s = 0; s < 32; s++) {
#pragma unroll
        for (int c = 0; c < 4; c++) {
            float4 m = M4[(size_t)(s * 4 + c) * 32 + lane];
            float b0, b1, b2, b3;
            if (c == 0) {
                b0 = __shfl_sync(FULL, ht[0].x, s); b1 = __shfl_sync(FULL, ht[1].x, s);
                b2 = __shfl_sync(FULL, ht[2].x, s); b3 = __shfl_sync(FULL, ht[3].x, s);
            } else if (c == 1) {
                b0 = __shfl_sync(FULL, ht[0].y, s); b1 = __shfl_sync(FULL, ht[1].y, s);
                b2 = __shfl_sync(FULL, ht[2].y, s); b3 = __shfl_sync(FULL, ht[3].y, s);
            } else if (c == 2) {
                b0 = __shfl_sync(FULL, ht[0].z, s); b1 = __shfl_sync(FULL, ht[1].z, s);
                b2 = __shfl_sync(FULL, ht[2].z, s); b3 = __shfl_sync(FULL, ht[3].z, s);
            } else {
                b0 = __shfl_sync(FULL, ht[0].w, s); b1 = __shfl_sync(FULL, ht[1].w, s);
                b2 = __shfl_sync(FULL, ht[2].w, s); b3 = __shfl_sync(FULL, ht[3].w, s);
            }
            u[0].x += b0 * m.x; u[0].y += b0 * m.y; u[0].z += b0 * m.z; u[0].w += b0 * m.w;
            u[1].x += b1 * m.x; u[1].y += b1 * m.y; u[1].z += b1 * m.z; u[1].w += b1 * m.w;
            u[2].x += b2 * m.x; u[2].y += b2 * m.y; u[2].z += b2 * m.z; u[2].w += b2 * m.w;
            u[3].x += b3 * m.x; u[3].y += b3 * m.y; u[3].z += b3 * m.z; u[3].w += b3 * m.w;
        }
    }

    // ---- per-node: e_k, softmax over 3, combine, store ----
#pragma unroll
    for (int q = 0; q < 4; q++) {
        int node = node0 + q;
        if (node >= n) break;
        float e0 = u[q].x * hv[q][0].x + u[q].y * hv[q][0].y + u[q].z * hv[q][0].z + u[q].w * hv[q][0].w;
        float e1 = u[q].x * hv[q][1].x + u[q].y * hv[q][1].y + u[q].z * hv[q][1].z + u[q].w * hv[q][1].w;
        float e2 = u[q].x * hv[q][2].x + u[q].y * hv[q][2].y + u[q].z * hv[q][2].z + u[q].w * hv[q][2].w;
#pragma unroll
        for (int o = 16; o; o >>= 1) {
            e0 += __shfl_xor_sync(FULL, e0, o);
            e1 += __shfl_xor_sync(FULL, e1, o);
            e2 += __shfl_xor_sync(FULL, e2, o);
        }
        const float sc = 0.0883883476483184f;  // 1/sqrt(128)
        e0 *= sc; e1 *= sc; e2 *= sc;
        float mx = fmaxf(e0, fmaxf(e1, e2));
        float a0 = __expf(e0 - mx), a1 = __expf(e1 - mx), a2 = __expf(e2 - mx);
        float is = 1.f / (a0 + a1 + a2);
        a0 *= is; a1 *= is; a2 *= is;

        float4 o4;
        o4.x = a0 * hv[q][0].x + a1 * hv[q][1].x + a2 * hv[q][2].x;
        o4.y = a0 * hv[q][0].y + a1 * hv[q][1].y + a2 * hv[q][2].y;
        o4.z = a0 * hv[q][0].z + a1 * hv[q][1].z + a2 * hv[q][2].z;
        o4.w = a0 * hv[q][0].w + a1 * hv[q][1].w + a2 * hv[q][2].w;
        *(float4*)(out + (size_t)node * D + lane * 4) = o4;
    }
}

// ---------------- launcher ----------------
extern "C" void kernel_launch(void* const* d_in, const int* in_sizes, int n_in,
                              void* d_out, int out_size) {
    const float* Nmat = (const float*)d_in[0];
    const float* W1_0 = (const float*)d_in[1];
    const float* W1_1 = (const float*)d_in[2];
    const float* W1_2 = (const float*)d_in[3];
    const float* w2_0 = (const float*)d_in[4];
    const float* w2_1 = (const float*)d_in[5];
    const float* w2_2 = (const float*)d_in[6];
    const float* Wq   = (const float*)d_in[7];
    const float* Wk   = (const float*)d_in[8];
    const int* s0 = (const int*)d_in[10];
    const int* d0 = (const int*)d_in[11];
    const int* s1 = (const int*)d_in[12];
    const int* d1 = (const int*)d_in[13];
    const int* s2 = (const int*)d_in[14];
    const int* d2 = (const int*)d_in[15];
    const int* tptr = (n_in > 16) ? (const int*)d_in[16] : nullptr;

    int n = in_sizes[0] / D;
    if (n > MAXN) n = MAXN;
    int e0 = in_sizes[10]; if (e0 > MAXE) e0 = MAXE;
    int e1 = in_sizes[12]; if (e1 > MAXE) e1 = MAXE;
    int e2 = in_sizes[14]; if (e2 > MAXE) e2 = MAXE;
    int emax = e0 > e1 ? (e0 > e2 ? e0 : e2) : (e1 > e2 ? e1 : e2);

    k_vec<<<6, 128>>>(W1_0, W1_1, W1_2, w2_0, w2_1, w2_2);
    k_M<<<128, 128>>>(Wq, Wk);
    k_zero<<<256, 256>>>();

    int nb_scores = (n + 63) / 64;  // 8 warps x 8 nodes per 256-thread block
    k_scores<<<nb_scores, 256>>>(Nmat, n);

    dim3 gc((emax + 255) / 256, 3);
    k_count<<<gc, 256>>>(d0, d1, d2, e0, e1, e2);
    k_scan<<<3, 1024>>>(n);
    k_scatter<<<gc, 256>>>(s0, s1, s2, d0, d1, d2, e0, e1, e2);

    int nb_agg = (n + 31) / 32;  // 8 warps x 4 nodes per 256-thread block
    k_agg<<<nb_agg, 256>>>(Nmat, (float*)d_out, n, tptr);
}

// round 6
// speedup vs baseline: 1.1909x; 1.1909x over previous
#include <cuda_runtime.h>
#include <cstdint>

#define D 128
#define MAXN 100000
#define MAXE 600000
#define NEG_SLOPE 0.01f
#define FULL 0xFFFFFFFFu

// ---------------- scratch (static device globals; no allocation) ----------------
static __device__ float g_vl[3][D];
static __device__ float g_vr[3][D];
static __device__ float g_M[D * D];                // Wq^T @ Wk
static __device__ float g_sl[3][MAXN];
static __device__ float g_sr[3][MAXN];
static __device__ int   g_cnt[3][MAXN];            // counts, then consumed as cursors
static __device__ int   g_off[3][MAXN + 1];
static __device__ int2  g_epack[3][MAXE];          // (src, exp-score bits), sorted by dst
static __device__ float g_h[3][(size_t)MAXN * D];  // per-relation aggregated features

__device__ __forceinline__ unsigned long long pack2(float lo, float hi) {
    unsigned long long r;
    asm("mov.b64 %0, {%1, %2};" : "=l"(r) : "f"(lo), "f"(hi));
    return r;
}
__device__ __forceinline__ float2 unpack2(unsigned long long v) {
    float2 r;
    asm("mov.b64 {%0, %1}, %2;" : "=f"(r.x), "=f"(r.y) : "l"(v));
    return r;
}
#define FMA2(d, a, b, c) \
    asm("fma.rn.f32x2 %0, %1, %2, %3;" : "=l"(d) : "l"(a), "l"(b), "l"(c))

// ---------------- K0a: v_l / v_r vectors ----------------
__global__ void k_vec(const float* __restrict__ W1_0, const float* __restrict__ W1_1,
                      const float* __restrict__ W1_2, const float* __restrict__ w2_0,
                      const float* __restrict__ w2_1, const float* __restrict__ w2_2) {
    int r = blockIdx.x >> 1;
    int half = blockIdx.x & 1;
    const float* W1 = (r == 0) ? W1_0 : (r == 1) ? W1_1 : W1_2;
    const float* w2 = ((r == 0) ? w2_0 : (r == 1) ? w2_1 : w2_2) + half * D;
    int j = threadIdx.x;
    float s = 0.f;
#pragma unroll 8
    for (int i = 0; i < D; i++) s += W1[i * D + j] * w2[i];
    if (half) g_vr[r][j] = s; else g_vl[r][j] = s;
}

// ---------------- K0b: M = Wq^T @ Wk ----------------
__global__ void k_M(const float* __restrict__ Wq, const float* __restrict__ Wk) {
    int dd = blockIdx.x;
    int j = threadIdx.x;
    float s = 0.f;
#pragma unroll 8
    for (int e = 0; e < D; e++) s += Wq[e * D + dd] * Wk[e * D + j];
    g_M[dd * D + j] = s;
}

// ---------------- K1: zero counts ----------------
__global__ void k_zero() {
    int i = blockIdx.x * blockDim.x + threadIdx.x;
    int tot = 3 * MAXN;
    int stride = gridDim.x * blockDim.x;
    for (; i < tot; i += stride) (&g_cnt[0][0])[i] = 0;
}

// ---------------- K2: per-node scores, warp per node ----------------
__global__ void k_scores(const float* __restrict__ Nmat, int n) {
    int w = (blockIdx.x * blockDim.x + threadIdx.x) >> 5;
    int lane = threadIdx.x & 31;
    if (w >= n) return;
    float4 x = ((const float4*)(Nmat + (size_t)w * D))[lane];
    float p0, p1, p2, p3, p4, p5;
    {
        float4 a = ((const float4*)g_vl[0])[lane];
        float4 b = ((const float4*)g_vr[0])[lane];
        p0 = x.x * a.x + x.y * a.y + x.z * a.z + x.w * a.w;
        p1 = x.x * b.x + x.y * b.y + x.z * b.z + x.w * b.w;
    }
    {
        float4 a = ((const float4*)g_vl[1])[lane];
        float4 b = ((const float4*)g_vr[1])[lane];
        p2 = x.x * a.x + x.y * a.y + x.z * a.z + x.w * a.w;
        p3 = x.x * b.x + x.y * b.y + x.z * b.z + x.w * b.w;
    }
    {
        float4 a = ((const float4*)g_vl[2])[lane];
        float4 b = ((const float4*)g_vr[2])[lane];
        p4 = x.x * a.x + x.y * a.y + x.z * a.z + x.w * a.w;
        p5 = x.x * b.x + x.y * b.y + x.z * b.z + x.w * b.w;
    }
#pragma unroll
    for (int o = 16; o; o >>= 1) {
        p0 += __shfl_xor_sync(FULL, p0, o);
        p1 += __shfl_xor_sync(FULL, p1, o);
        p2 += __shfl_xor_sync(FULL, p2, o);
        p3 += __shfl_xor_sync(FULL, p3, o);
        p4 += __shfl_xor_sync(FULL, p4, o);
        p5 += __shfl_xor_sync(FULL, p5, o);
    }
    if (lane == 0) {
        g_sl[0][w] = p0; g_sr[0][w] = p1;
        g_sl[1][w] = p2; g_sr[1][w] = p3;
        g_sl[2][w] = p4; g_sr[2][w] = p5;
    }
}

// ---------------- K3: in-degree counts ----------------
__global__ void k_count(const int* __restrict__ d0, const int* __restrict__ d1,
                        const int* __restrict__ d2, int e0, int e1, int e2) {
    int r = blockIdx.y;
    const int* dst = (r == 0) ? d0 : (r == 1) ? d1 : d2;
    int E = (r == 0) ? e0 : (r == 1) ? e1 : e2;
    int t = blockIdx.x * blockDim.x + threadIdx.x;
    if (t >= E) return;
    atomicAdd(&g_cnt[r][dst[t]], 1);
}

// ---------------- K4: exclusive scan -> CSR offsets (1 block per relation) ----------------
__global__ void k_scan(int n) {
    int r = blockIdx.x;
    __shared__ int warpsum[32];
    int tid = threadIdx.x;
    int lane = tid & 31, wid = tid >> 5;
    int chunk = (n + 1023) >> 10;
    int beg = tid * chunk;
    int end = beg + chunk; if (end > n) end = n;
    if (beg > n) beg = n;
    int loc = 0;
    for (int i = beg; i < end; i++) loc += g_cnt[r][i];
    int v = loc;
#pragma unroll
    for (int o = 1; o < 32; o <<= 1) {
        int t = __shfl_up_sync(FULL, v, o);
        if (lane >= o) v += t;
    }
    if (lane == 31) warpsum[wid] = v;
    __syncthreads();
    if (wid == 0) {
        int s = warpsum[lane];
#pragma unroll
        for (int o = 1; o < 32; o <<= 1) {
            int t = __shfl_up_sync(FULL, s, o);
            if (lane >= o) s += t;
        }
        warpsum[lane] = s;
    }
    __syncthreads();
    int excl = v - loc + (wid ? warpsum[wid - 1] : 0);
    int run = excl;
    for (int i = beg; i < end; i++) {
        g_off[r][i] = run;
        run += g_cnt[r][i];
    }
    if (end == n) g_off[r][n] = run;
}

// ---------------- K5: scatter edges (counts consumed as cursors via atomicSub) ----------------
__global__ void k_scatter(const int* __restrict__ s0, const int* __restrict__ s1,
                          const int* __restrict__ s2, const int* __restrict__ d0,
                          const int* __restrict__ d1, const int* __restrict__ d2,
                          int e0, int e1, int e2) {
    int r = blockIdx.y;
    const int* src = (r == 0) ? s0 : (r == 1) ? s1 : s2;
    const int* dst = (r == 0) ? d0 : (r == 1) ? d1 : d2;
    int E = (r == 0) ? e0 : (r == 1) ? e1 : e2;
    int t = blockIdx.x * blockDim.x + threadIdx.x;
    if (t >= E) return;
    int s = src[t];
    int d = dst[t];
    float ev = g_sl[r][s] + g_sr[r][d];
    ev = (ev >= 0.f) ? ev : NEG_SLOPE * ev;
    float ex = __expf(ev);
    int pos = g_off[r][d] + atomicSub(&g_cnt[r][d], 1) - 1;
    g_epack[r][pos] = make_int2(s, __float_as_int(ex));
}

// ---------------- K6: aggregation only (warp per node, low regs, high occupancy) ----------------
__global__ void __launch_bounds__(256) k_aggA(const float* __restrict__ Nmat, int n) {
    int w = (blockIdx.x * blockDim.x + threadIdx.x) >> 5;
    int lane = threadIdx.x & 31;
    if (w >= n) return;
    const float4* N4 = (const float4*)Nmat;
#pragma unroll
    for (int r = 0; r < 3; r++) {
        int beg = g_off[r][w];
        int end = g_off[r][w + 1];
        const int2* ep = g_epack[r];
        float4 acc = make_float4(0.f, 0.f, 0.f, 0.f);
        float den = 0.f;
        for (int base = beg; base < end; base += 32) {
            int cnt = end - base; if (cnt > 32) cnt = 32;
            int2 evp = make_int2(0, 0);
            if (lane < cnt) evp = ep[base + lane];
#pragma unroll 4
            for (int j = 0; j < cnt; j++) {
                int s = __shfl_sync(FULL, evp.x, j);
                float ex = __int_as_float(__shfl_sync(FULL, evp.y, j));
                float4 nv = N4[(size_t)s * 32 + lane];
                acc.x += ex * nv.x; acc.y += ex * nv.y;
                acc.z += ex * nv.z; acc.w += ex * nv.w;
                den += ex;
            }
        }
        float iv = (den > 0.f) ? (1.f / den) : 0.f;
        float4 h4 = make_float4(acc.x * iv, acc.y * iv, acc.z * iv, acc.w * iv);
        ((float4*)g_h[r])[(size_t)w * 32 + lane] = h4;
    }
}

// ---------------- K7: attention (warp per 8 nodes; f32x2 GEMV against M) ----------------
__global__ void __launch_bounds__(256)
k_attn(float* __restrict__ out, int n, const int* __restrict__ tptr) {
    int w = (blockIdx.x * blockDim.x + threadIdx.x) >> 5;
    int lane = threadIdx.x & 31;
    int node0 = w * 8;
    if (node0 >= n) return;

    int t = tptr ? tptr[0] : 0;
    t = (t < 0) ? 0 : ((t > 2) ? 2 : t);
    const float4* Ht4 = (const float4*)g_h[t];

    // load ht for 8 nodes (distributed float4 per lane)
    float4 ht[8];
#pragma unroll
    for (int q = 0; q < 8; q++) {
        int node = node0 + q;
        ht[q] = (node < n) ? Ht4[(size_t)node * 32 + lane]
                           : make_float4(0.f, 0.f, 0.f, 0.f);
    }

    // u[q] = ht[q] @ M, packed f32x2 accumulators
    unsigned long long u01[8], u23[8];
    unsigned long long z = pack2(0.f, 0.f);
#pragma unroll
    for (int q = 0; q < 8; q++) { u01[q] = z; u23[q] = z; }

    const longlong2* M2 = (const longlong2*)g_M;
#pragma unroll 4
    for (int s = 0; s < 32; s++) {
#pragma unroll
        for (int c = 0; c < 4; c++) {
            longlong2 ml = M2[(size_t)(s * 4 + c) * 32 + lane];
            unsigned long long m01 = (unsigned long long)ml.x;
            unsigned long long m23 = (unsigned long long)ml.y;
#pragma unroll
            for (int q = 0; q < 8; q++) {
                float b = (c == 0) ? __shfl_sync(FULL, ht[q].x, s)
                        : (c == 1) ? __shfl_sync(FULL, ht[q].y, s)
                        : (c == 2) ? __shfl_sync(FULL, ht[q].z, s)
                                   : __shfl_sync(FULL, ht[q].w, s);
                unsigned long long bb = pack2(b, b);
                FMA2(u01[q], m01, bb, u01[q]);
                FMA2(u23[q], m23, bb, u23[q]);
            }
        }
    }

    const float4* H0 = (const float4*)g_h[0];
    const float4* H1 = (const float4*)g_h[1];
    const float4* H2 = (const float4*)g_h[2];
    const float sc = 0.0883883476483184f;  // 1/sqrt(128)

#pragma unroll
    for (int q = 0; q < 8; q++) {
        int node = node0 + q;
        if (node >= n) break;
        float2 ua = unpack2(u01[q]);
        float2 ub = unpack2(u23[q]);
        float4 h0 = H0[(size_t)node * 32 + lane];
        float4 h1 = H1[(size_t)node * 32 + lane];
        float4 h2 = H2[(size_t)node * 32 + lane];
        float e0 = ua.x * h0.x + ua.y * h0.y + ub.x * h0.z + ub.y * h0.w;
        float e1 = ua.x * h1.x + ua.y * h1.y + ub.x * h1.z + ub.y * h1.w;
        float e2 = ua.x * h2.x + ua.y * h2.y + ub.x * h2.z + ub.y * h2.w;
#pragma unroll
        for (int o = 16; o; o >>= 1) {
            e0 += __shfl_xor_sync(FULL, e0, o);
            e1 += __shfl_xor_sync(FULL, e1, o);
            e2 += __shfl_xor_sync(FULL, e2, o);
        }
        e0 *= sc; e1 *= sc; e2 *= sc;
        float mx = fmaxf(e0, fmaxf(e1, e2));
        float a0 = __expf(e0 - mx), a1 = __expf(e1 - mx), a2 = __expf(e2 - mx);
        float is = 1.f / (a0 + a1 + a2);
        a0 *= is; a1 *= is; a2 *= is;

        float4 o4;
        o4.x = a0 * h0.x + a1 * h1.x + a2 * h2.x;
        o4.y = a0 * h0.y + a1 * h1.y + a2 * h2.y;
        o4.z = a0 * h0.z + a1 * h1.z + a2 * h2.z;
        o4.w = a0 * h0.w + a1 * h1.w + a2 * h2.w;
        *(float4*)(out + (size_t)node * D + lane * 4) = o4;
    }
}

// ---------------- launcher ----------------
extern "C" void kernel_launch(void* const* d_in, const int* in_sizes, int n_in,
                              void* d_out, int out_size) {
    const float* Nmat = (const float*)d_in[0];
    const float* W1_0 = (const float*)d_in[1];
    const float* W1_1 = (const float*)d_in[2];
    const float* W1_2 = (const float*)d_in[3];
    const float* w2_0 = (const float*)d_in[4];
    const float* w2_1 = (const float*)d_in[5];
    const float* w2_2 = (const float*)d_in[6];
    const float* Wq   = (const float*)d_in[7];
    const float* Wk   = (const float*)d_in[8];
    const int* s0 = (const int*)d_in[10];
    const int* d0 = (const int*)d_in[11];
    const int* s1 = (const int*)d_in[12];
    const int* d1 = (const int*)d_in[13];
    const int* s2 = (const int*)d_in[14];
    const int* d2 = (const int*)d_in[15];
    const int* tptr = (n_in > 16) ? (const int*)d_in[16] : nullptr;

    int n = in_sizes[0] / D;
    if (n > MAXN) n = MAXN;
    int e0 = in_sizes[10]; if (e0 > MAXE) e0 = MAXE;
    int e1 = in_sizes[12]; if (e1 > MAXE) e1 = MAXE;
    int e2 = in_sizes[14]; if (e2 > MAXE) e2 = MAXE;
    int emax = e0 > e1 ? (e0 > e2 ? e0 : e2) : (e1 > e2 ? e1 : e2);

    k_vec<<<6, 128>>>(W1_0, W1_1, W1_2, w2_0, w2_1, w2_2);
    k_M<<<128, 128>>>(Wq, Wk);
    k_zero<<<256, 256>>>();

    int nb_scores = (n + 7) / 8;
    k_scores<<<nb_scores, 256>>>(Nmat, n);

    dim3 gc((emax + 255) / 256, 3);
    k_count<<<gc, 256>>>(d0, d1, d2, e0, e1, e2);
    k_scan<<<3, 1024>>>(n);
    k_scatter<<<gc, 256>>>(s0, s1, s2, d0, d1, d2, e0, e1, e2);

    int nb_agg = (n + 7) / 8;           // warp per node
    k_aggA<<<nb_agg, 256>>>(Nmat, n);

    int nb_attn = (n + 63) / 64;        // 8 warps x 8 nodes
    k_attn<<<nb_attn, 256>>>((float*)d_out, n, tptr);
}

// round 8
// speedup vs baseline: 1.2586x; 1.0569x over previous
#include <cuda_runtime.h>
#include <cstdint>

#define D 128
#define MAXN 100000
#define MAXE 600000
#define NEG_SLOPE 0.01f
#define FULL 0xFFFFFFFFu

// ---------------- scratch (static device globals; no allocation) ----------------
static __device__ float g_vl[3][D];
static __device__ float g_vr[3][D];
static __device__ float g_M[D * D];                    // Wq^T @ Wk
static __device__ float g_sl[3][MAXN];
static __device__ float g_sr[3][MAXN];
static __device__ int   g_cnt[3][MAXN];                // counts, then consumed as cursors
static __device__ int   g_off[3][MAXN + 1];
static __device__ int2  g_epack[3][MAXE];              // (src, exp-score bits), by dst
static __device__ float g_h[(size_t)MAXN * 3 * D];     // interleaved [node][r][D]

__device__ __forceinline__ unsigned long long pack2(float lo, float hi) {
    unsigned long long r;
    asm("mov.b64 %0, {%1, %2};" : "=l"(r) : "f"(lo), "f"(hi));
    return r;
}
__device__ __forceinline__ float2 unpack2(unsigned long long v) {
    float2 r;
    asm("mov.b64 {%0, %1}, %2;" : "=f"(r.x), "=f"(r.y) : "l"(v));
    return r;
}
#define FMA2(d, a, b, c) \
    asm("fma.rn.f32x2 %0, %1, %2, %3;" : "=l"(d) : "l"(a), "l"(b), "l"(c))

// ---------------- K1: fused prep (vec | M | zero), 128-thread blocks ----------------
// blocks [0,6): v_l/v_r ; blocks [6,134): M ; blocks [134,...): zero counts
__global__ void k_prep(const float* __restrict__ W1_0, const float* __restrict__ W1_1,
                       const float* __restrict__ W1_2, const float* __restrict__ w2_0,
                       const float* __restrict__ w2_1, const float* __restrict__ w2_2,
                       const float* __restrict__ Wq, const float* __restrict__ Wk) {
    int b = blockIdx.x;
    if (b < 6) {
        int r = b >> 1;
        int half = b & 1;
        const float* W1 = (r == 0) ? W1_0 : (r == 1) ? W1_1 : W1_2;
        const float* w2 = ((r == 0) ? w2_0 : (r == 1) ? w2_1 : w2_2) + half * D;
        int j = threadIdx.x;
        float s = 0.f;
#pragma unroll 8
        for (int i = 0; i < D; i++) s += W1[i * D + j] * w2[i];
        if (half) g_vr[r][j] = s; else g_vl[r][j] = s;
    } else if (b < 134) {
        int dd = b - 6;
        int j = threadIdx.x;
        float s = 0.f;
#pragma unroll 8
        for (int e = 0; e < D; e++) s += Wq[e * D + dd] * Wk[e * D + j];
        g_M[dd * D + j] = s;
    } else {
        int i = (b - 134) * blockDim.x + threadIdx.x;
        int tot = 3 * MAXN;
        int stride = (gridDim.x - 134) * blockDim.x;
        for (; i < tot; i += stride) (&g_cnt[0][0])[i] = 0;
    }
}

// ---------------- K2: fused scores (warp/node) + in-degree counts ----------------
__global__ void __launch_bounds__(256)
k_scores_count(const float* __restrict__ Nmat, int n, int nbs, int ebpr,
               const int* __restrict__ d0, const int* __restrict__ d1,
               const int* __restrict__ d2, int e0, int e1, int e2) {
    int b = blockIdx.x;
    if (b < nbs) {
        int w = (b * 256 + threadIdx.x) >> 5;
        int lane = threadIdx.x & 31;
        if (w >= n) return;
        float4 x = ((const float4*)(Nmat + (size_t)w * D))[lane];
        float p0, p1, p2, p3, p4, p5;
        {
            float4 a = ((const float4*)g_vl[0])[lane];
            float4 c = ((const float4*)g_vr[0])[lane];
            p0 = x.x * a.x + x.y * a.y + x.z * a.z + x.w * a.w;
            p1 = x.x * c.x + x.y * c.y + x.z * c.z + x.w * c.w;
        }
        {
            float4 a = ((const float4*)g_vl[1])[lane];
            float4 c = ((const float4*)g_vr[1])[lane];
            p2 = x.x * a.x + x.y * a.y + x.z * a.z + x.w * a.w;
            p3 = x.x * c.x + x.y * c.y + x.z * c.z + x.w * c.w;
        }
        {
            float4 a = ((const float4*)g_vl[2])[lane];
            float4 c = ((const float4*)g_vr[2])[lane];
            p4 = x.x * a.x + x.y * a.y + x.z * a.z + x.w * a.w;
            p5 = x.x * c.x + x.y * c.y + x.z * c.z + x.w * c.w;
        }
#pragma unroll
        for (int o = 16; o; o >>= 1) {
            p0 += __shfl_xor_sync(FULL, p0, o);
            p1 += __shfl_xor_sync(FULL, p1, o);
            p2 += __shfl_xor_sync(FULL, p2, o);
            p3 += __shfl_xor_sync(FULL, p3, o);
            p4 += __shfl_xor_sync(FULL, p4, o);
            p5 += __shfl_xor_sync(FULL, p5, o);
        }
        if (lane == 0) {
            g_sl[0][w] = p0; g_sr[0][w] = p1;
            g_sl[1][w] = p2; g_sr[1][w] = p3;
            g_sl[2][w] = p4; g_sr[2][w] = p5;
        }
    } else {
        int cb = b - nbs;
        int r = cb / ebpr;
        int t = (cb - r * ebpr) * 256 + threadIdx.x;
        const int* dst = (r == 0) ? d0 : (r == 1) ? d1 : d2;
        int E = (r == 0) ? e0 : (r == 1) ? e1 : e2;
        if (t >= E) return;
        atomicAdd(&g_cnt[r][dst[t]], 1);
    }
}

// ---------------- K3: exclusive scan -> CSR offsets (1 block per relation) ----------------
__global__ void k_scan(int n) {
    int r = blockIdx.x;
    __shared__ int warpsum[32];
    int tid = threadIdx.x;
    int lane = tid & 31, wid = tid >> 5;
    int chunk = (n + 1023) >> 10;
    int beg = tid * chunk;
    int end = beg + chunk; if (end > n) end = n;
    if (beg > n) beg = n;
    int loc = 0;
    for (int i = beg; i < end; i++) loc += g_cnt[r][i];
    int v = loc;
#pragma unroll
    for (int o = 1; o < 32; o <<= 1) {
        int t = __shfl_up_sync(FULL, v, o);
        if (lane >= o) v += t;
    }
    if (lane == 31) warpsum[wid] = v;
    __syncthreads();
    if (wid == 0) {
        int s = warpsum[lane];
#pragma unroll
        for (int o = 1; o < 32; o <<= 1) {
            int t = __shfl_up_sync(FULL, s, o);
            if (lane >= o) s += t;
        }
        warpsum[lane] = s;
    }
    __syncthreads();
    int excl = v - loc + (wid ? warpsum[wid - 1] : 0);
    int run = excl;
    for (int i = beg; i < end; i++) {
        g_off[r][i] = run;
        run += g_cnt[r][i];
    }
    if (end == n) g_off[r][n] = run;
}

// ---------------- K4: scatter edges (counts consumed as cursors) ----------------
__global__ void k_scatter(const int* __restrict__ s0, const int* __restrict__ s1,
                          const int* __restrict__ s2, const int* __restrict__ d0,
                          const int* __restrict__ d1, const int* __restrict__ d2,
                          int e0, int e1, int e2) {
    int r = blockIdx.y;
    const int* src = (r == 0) ? s0 : (r == 1) ? s1 : s2;
    const int* dst = (r == 0) ? d0 : (r == 1) ? d1 : d2;
    int E = (r == 0) ? e0 : (r == 1) ? e1 : e2;
    int t = blockIdx.x * blockDim.x + threadIdx.x;
    if (t >= E) return;
    int s = src[t];
    int d = dst[t];
    float ev = g_sl[r][s] + g_sr[r][d];
    ev = (ev >= 0.f) ? ev : NEG_SLOPE * ev;
    float ex = __expf(ev);
    int pos = g_off[r][d] + atomicSub(&g_cnt[r][d], 1) - 1;
    g_epack[r][pos] = make_int2(s, __float_as_int(ex));
}

// ---------------- K5: aggregation (warp per node) -> interleaved g_h ----------------
__global__ void __launch_bounds__(256) k_aggA(const float* __restrict__ Nmat, int n) {
    int w = (blockIdx.x * blockDim.x + threadIdx.x) >> 5;
    int lane = threadIdx.x & 31;
    if (w >= n) return;
    const float4* N4 = (const float4*)Nmat;
    float4* H4 = (float4*)(g_h + (size_t)w * 3 * D);
#pragma unroll
    for (int r = 0; r < 3; r++) {
        int beg = g_off[r][w];
        int end = g_off[r][w + 1];
        const int2* ep = g_epack[r];
        float4 acc = make_float4(0.f, 0.f, 0.f, 0.f);
        float den = 0.f;
        for (int base = beg; base < end; base += 32) {
            int cnt = end - base; if (cnt > 32) cnt = 32;
            int2 evp = make_int2(0, 0);
            if (lane < cnt) evp = ep[base + lane];
#pragma unroll 4
            for (int j = 0; j < cnt; j++) {
                int s = __shfl_sync(FULL, evp.x, j);
                float ex = __int_as_float(__shfl_sync(FULL, evp.y, j));
                float4 nv = N4[(size_t)s * 32 + lane];
                acc.x += ex * nv.x; acc.y += ex * nv.y;
                acc.z += ex * nv.z; acc.w += ex * nv.w;
                den += ex;
            }
        }
        float iv = (den > 0.f) ? (1.f / den) : 0.f;
        H4[r * 32 + lane] = make_float4(acc.x * iv, acc.y * iv, acc.z * iv, acc.w * iv);
    }
}

// ---------------- K6: attention (warp per 8 nodes; f32x2 GEMV against M) ----------------
__global__ void __launch_bounds__(256)
k_attn(float* __restrict__ out, int n, const int* __restrict__ tptr) {
    int w = (blockIdx.x * blockDim.x + threadIdx.x) >> 5;
    int lane = threadIdx.x & 31;
    int node0 = w * 8;
    if (node0 >= n) return;

    int t = tptr ? tptr[0] : 0;
    t = (t < 0) ? 0 : ((t > 2) ? 2 : t);

    // load ht for 8 nodes (distributed float4 per lane) from interleaved layout
    float4 ht[8];
#pragma unroll
    for (int q = 0; q < 8; q++) {
        int node = node0 + q;
        ht[q] = (node < n)
            ? ((const float4*)(g_h + ((size_t)node * 3 + t) * D))[lane]
            : make_float4(0.f, 0.f, 0.f, 0.f);
    }

    // u[q] = ht[q] @ M, packed f32x2 accumulators
    unsigned long long u01[8], u23[8];
    unsigned long long z = pack2(0.f, 0.f);
#pragma unroll
    for (int q = 0; q < 8; q++) { u01[q] = z; u23[q] = z; }

    const longlong2* M2 = (const longlong2*)g_M;
#pragma unroll 4
    for (int s = 0; s < 32; s++) {
#pragma unroll
        for (int c = 0; c < 4; c++) {
            longlong2 ml = M2[(size_t)(s * 4 + c) * 32 + lane];
            unsigned long long m01 = (unsigned long long)ml.x;
            unsigned long long m23 = (unsigned long long)ml.y;
#pragma unroll
            for (int q = 0; q < 8; q++) {
                float b = (c == 0) ? __shfl_sync(FULL, ht[q].x, s)
                        : (c == 1) ? __shfl_sync(FULL, ht[q].y, s)
                        : (c == 2) ? __shfl_sync(FULL, ht[q].z, s)
                                   : __shfl_sync(FULL, ht[q].w, s);
                unsigned long long bb = pack2(b, b);
                FMA2(u01[q], m01, bb, u01[q]);
                FMA2(u23[q], m23, bb, u23[q]);
            }
        }
    }

    const float sc = 0.0883883476483184f;  // 1/sqrt(128)

#pragma unroll
    for (int q = 0; q < 8; q++) {
        int node = node0 + q;
        if (node >= n) break;
        float2 ua = unpack2(u01[q]);
        float2 ub = unpack2(u23[q]);
        const float4* Hn = (const float4*)(g_h + (size_t)node * 3 * D);
        float4 h0 = Hn[0 * 32 + lane];
        float4 h1 = Hn[1 * 32 + lane];
        float4 h2 = Hn[2 * 32 + lane];
        float e0 = ua.x * h0.x + ua.y * h0.y + ub.x * h0.z + ub.y * h0.w;
        float e1 = ua.x * h1.x + ua.y * h1.y + ub.x * h1.z + ub.y * h1.w;
        float e2 = ua.x * h2.x + ua.y * h2.y + ub.x * h2.z + ub.y * h2.w;
#pragma unroll
        for (int o = 16; o; o >>= 1) {
            e0 += __shfl_xor_sync(FULL, e0, o);
            e1 += __shfl_xor_sync(FULL, e1, o);
            e2 += __shfl_xor_sync(FULL, e2, o);
        }
        e0 *= sc; e1 *= sc; e2 *= sc;
        float mx = fmaxf(e0, fmaxf(e1, e2));
        float a0 = __expf(e0 - mx), a1 = __expf(e1 - mx), a2 = __expf(e2 - mx);
        float is = 1.f / (a0 + a1 + a2);
        a0 *= is; a1 *= is; a2 *= is;

        float4 o4;
        o4.x = a0 * h0.x + a1 * h1.x + a2 * h2.x;
        o4.y = a0 * h0.y + a1 * h1.y + a2 * h2.y;
        o4.z = a0 * h0.z + a1 * h1.z + a2 * h2.z;
        o4.w = a0 * h0.w + a1 * h1.w + a2 * h2.w;
        *(float4*)(out + (size_t)node * D + lane * 4) = o4;
    }
}

// ---------------- launcher ----------------
extern "C" void kernel_launch(void* const* d_in, const int* in_sizes, int n_in,
                              void* d_out, int out_size) {
    const float* Nmat = (const float*)d_in[0];
    const float* W1_0 = (const float*)d_in[1];
    const float* W1_1 = (const float*)d_in[2];
    const float* W1_2 = (const float*)d_in[3];
    const float* w2_0 = (const float*)d_in[4];
    const float* w2_1 = (const float*)d_in[5];
    const float* w2_2 = (const float*)d_in[6];
    const float* Wq   = (const float*)d_in[7];
    const float* Wk   = (const float*)d_in[8];
    const int* s0 = (const int*)d_in[10];
    const int* d0 = (const int*)d_in[11];
    const int* s1 = (const int*)d_in[12];
    const int* d1 = (const int*)d_in[13];
    const int* s2 = (const int*)d_in[14];
    const int* d2 = (const int*)d_in[15];
    const int* tptr = (n_in > 16) ? (const int*)d_in[16] : nullptr;

    int n = in_sizes[0] / D;
    if (n > MAXN) n = MAXN;
    int e0 = in_sizes[10]; if (e0 > MAXE) e0 = MAXE;
    int e1 = in_sizes[12]; if (e1 > MAXE) e1 = MAXE;
    int e2 = in_sizes[14]; if (e2 > MAXE) e2 = MAXE;
    int emax = e0 > e1 ? (e0 > e2 ? e0 : e2) : (e1 > e2 ? e1 : e2);

    // 1: prep (vec | M | zero)
    k_prep<<<134 + 1172, 128>>>(W1_0, W1_1, W1_2, w2_0, w2_1, w2_2, Wq, Wk);

    // 2: scores + counts fused
    int nbs = (n + 7) / 8;
    int ebpr = (emax + 255) / 256;
    k_scores_count<<<nbs + 3 * ebpr, 256>>>(Nmat, n, nbs, ebpr,
                                            d0, d1, d2, e0, e1, e2);
    // 3: scan
    k_scan<<<3, 1024>>>(n);

    // 4: scatter  (<- profiled slot)
    dim3 gc(ebpr, 3);
    k_scatter<<<gc, 256>>>(s0, s1, s2, d0, d1, d2, e0, e1, e2);

    // 5: aggregation
    int nb_agg = (n + 7) / 8;
    k_aggA<<<nb_agg, 256>>>(Nmat, n);

    // 6: attention
    int nb_attn = (n + 63) / 64;
    k_attn<<<nb_attn, 256>>>((float*)d_out, n, tptr);
}

// round 15
// speedup vs baseline: 1.2842x; 1.0203x over previous
#include <cuda_runtime.h>
#include <cstdint>

#define D 128
#define MAXN 100000
#define MAXE 600000
#define NEG_SLOPE 0.01f
#define FULL 0xFFFFFFFFu

// ---------------- scratch (static device globals; no allocation) ----------------
static __device__ float g_vl[3][D];
static __device__ float g_vr[3][D];
static __device__ float g_M[D * D];                    // Wq^T @ Wk
static __device__ float g_sl[3][MAXN];
static __device__ float g_sr[3][MAXN];
static __device__ int   g_cnt[3][MAXN];                // counts, then consumed as cursors
static __device__ int   g_off[3][MAXN + 1];
static __device__ int2  g_epack[3][MAXE];              // (src, exp-score bits), by dst
static __device__ float g_h[(size_t)MAXN * 3 * D];     // interleaved [node][r][D]

__device__ __forceinline__ unsigned long long pack2(float lo, float hi) {
    unsigned long long r;
    asm("mov.b64 %0, {%1, %2};" : "=l"(r) : "f"(lo), "f"(hi));
    return r;
}
__device__ __forceinline__ float2 unpack2(unsigned long long v) {
    float2 r;
    asm("mov.b64 {%0, %1}, %2;" : "=f"(r.x), "=f"(r.y) : "l"(v));
    return r;
}
#define FMA2(d, a, b, c) \
    asm("fma.rn.f32x2 %0, %1, %2, %3;" : "=l"(d) : "l"(a), "l"(b), "l"(c))

// ---------------- K1: fused prep (vec | M | zero), 128-thread blocks ----------------
// blocks [0,6): v_l/v_r ; blocks [6,134): M ; blocks [134,...): zero counts
__global__ void k_prep(const float* __restrict__ W1_0, const float* __restrict__ W1_1,
                       const float* __restrict__ W1_2, const float* __restrict__ w2_0,
                       const float* __restrict__ w2_1, const float* __restrict__ w2_2,
                       const float* __restrict__ Wq, const float* __restrict__ Wk) {
    int b = blockIdx.x;
    if (b < 6) {
        int r = b >> 1;
        int half = b & 1;
        const float* W1 = (r == 0) ? W1_0 : (r == 1) ? W1_1 : W1_2;
        const float* w2 = ((r == 0) ? w2_0 : (r == 1) ? w2_1 : w2_2) + half * D;
        int j = threadIdx.x;
        float s = 0.f;
#pragma unroll 8
        for (int i = 0; i < D; i++) s += W1[i * D + j] * w2[i];
        if (half) g_vr[r][j] = s; else g_vl[r][j] = s;
    } else if (b < 134) {
        int dd = b - 6;
        int j = threadIdx.x;
        float s = 0.f;
#pragma unroll 8
        for (int e = 0; e < D; e++) s += Wq[e * D + dd] * Wk[e * D + j];
        g_M[dd * D + j] = s;
    } else {
        int i = (b - 134) * blockDim.x + threadIdx.x;
        int tot = 3 * MAXN;
        int stride = (gridDim.x - 134) * blockDim.x;
        for (; i < tot; i += stride) (&g_cnt[0][0])[i] = 0;
    }
}

// ---------------- K2: fused scores (warp/node) + in-degree counts ----------------
__global__ void __launch_bounds__(256)
k_scores_count(const float* __restrict__ Nmat, int n, int nbs, int ebpr,
               const int* __restrict__ d0, const int* __restrict__ d1,
               const int* __restrict__ d2, int e0, int e1, int e2) {
    int b = blockIdx.x;
    if (b < nbs) {
        int w = (b * 256 + threadIdx.x) >> 5;
        int lane = threadIdx.x & 31;
        if (w >= n) return;
        float4 x = ((const float4*)(Nmat + (size_t)w * D))[lane];
        float p0, p1, p2, p3, p4, p5;
        {
            float4 a = ((const float4*)g_vl[0])[lane];
            float4 c = ((const float4*)g_vr[0])[lane];
            p0 = x.x * a.x + x.y * a.y + x.z * a.z + x.w * a.w;
            p1 = x.x * c.x + x.y * c.y + x.z * c.z + x.w * c.w;
        }
        {
            float4 a = ((const float4*)g_vl[1])[lane];
            float4 c = ((const float4*)g_vr[1])[lane];
            p2 = x.x * a.x + x.y * a.y + x.z * a.z + x.w * a.w;
            p3 = x.x * c.x + x.y * c.y + x.z * c.z + x.w * c.w;
        }
        {
            float4 a = ((const float4*)g_vl[2])[lane];
            float4 c = ((const float4*)g_vr[2])[lane];
            p4 = x.x * a.x + x.y * a.y + x.z * a.z + x.w * a.w;
            p5 = x.x * c.x + x.y * c.y + x.z * c.z + x.w * c.w;
        }
#pragma unroll
        for (int o = 16; o; o >>= 1) {
            p0 += __shfl_xor_sync(FULL, p0, o);
            p1 += __shfl_xor_sync(FULL, p1, o);
            p2 += __shfl_xor_sync(FULL, p2, o);
            p3 += __shfl_xor_sync(FULL, p3, o);
            p4 += __shfl_xor_sync(FULL, p4, o);
            p5 += __shfl_xor_sync(FULL, p5, o);
        }
        if (lane == 0) {
            g_sl[0][w] = p0; g_sr[0][w] = p1;
            g_sl[1][w] = p2; g_sr[1][w] = p3;
            g_sl[2][w] = p4; g_sr[2][w] = p5;
        }
    } else {
        int cb = b - nbs;
        int r = cb / ebpr;
        int t = (cb - r * ebpr) * 256 + threadIdx.x;
        const int* dst = (r == 0) ? d0 : (r == 1) ? d1 : d2;
        int E = (r == 0) ? e0 : (r == 1) ? e1 : e2;
        if (t >= E) return;
        atomicAdd(&g_cnt[r][dst[t]], 1);
    }
}

// ---------------- K3: exclusive scan -> CSR offsets (1 block per relation) ----------------
__global__ void k_scan(int n) {
    int r = blockIdx.x;
    __shared__ int warpsum[32];
    int tid = threadIdx.x;
    int lane = tid & 31, wid = tid >> 5;
    int chunk = (n + 1023) >> 10;
    int beg = tid * chunk;
    int end = beg + chunk; if (end > n) end = n;
    if (beg > n) beg = n;
    int loc = 0;
    for (int i = beg; i < end; i++) loc += g_cnt[r][i];
    int v = loc;
#pragma unroll
    for (int o = 1; o < 32; o <<= 1) {
        int t = __shfl_up_sync(FULL, v, o);
        if (lane >= o) v += t;
    }
    if (lane == 31) warpsum[wid] = v;
    __syncthreads();
    if (wid == 0) {
        int s = warpsum[lane];
#pragma unroll
        for (int o = 1; o < 32; o <<= 1) {
            int t = __shfl_up_sync(FULL, s, o);
            if (lane >= o) s += t;
        }
        warpsum[lane] = s;
    }
    __syncthreads();
    int excl = v - loc + (wid ? warpsum[wid - 1] : 0);
    int run = excl;
    for (int i = beg; i < end; i++) {
        g_off[r][i] = run;
        run += g_cnt[r][i];
    }
    if (end == n) g_off[r][n] = run;
}

// ---------------- K4: scatter edges (counts consumed as cursors) ----------------
__global__ void k_scatter(const int* __restrict__ s0, const int* __restrict__ s1,
                          const int* __restrict__ s2, const int* __restrict__ d0,
                          const int* __restrict__ d1, const int* __restrict__ d2,
                          int e0, int e1, int e2) {
    int r = blockIdx.y;
    const int* src = (r == 0) ? s0 : (r == 1) ? s1 : s2;
    const int* dst = (r == 0) ? d0 : (r == 1) ? d1 : d2;
    int E = (r == 0) ? e0 : (r == 1) ? e1 : e2;
    int t = blockIdx.x * blockDim.x + threadIdx.x;
    if (t >= E) return;
    int s = src[t];
    int d = dst[t];
    float ev = g_sl[r][s] + g_sr[r][d];
    ev = (ev >= 0.f) ? ev : NEG_SLOPE * ev;
    float ex = __expf(ev);
    int pos = g_off[r][d] + atomicSub(&g_cnt[r][d], 1) - 1;
    g_epack[r][pos] = make_int2(s, __float_as_int(ex));
}

// ---------------- K5: aggregation (warp per node) -> interleaved g_h ----------------
__global__ void __launch_bounds__(256) k_aggA(const float* __restrict__ Nmat, int n) {
    int w = (blockIdx.x * blockDim.x + threadIdx.x) >> 5;
    int lane = threadIdx.x & 31;
    if (w >= n) return;
    const float4* N4 = (const float4*)Nmat;
    float4* H4 = (float4*)(g_h + (size_t)w * 3 * D);
#pragma unroll
    for (int r = 0; r < 3; r++) {
        int beg = g_off[r][w];
        int end = g_off[r][w + 1];
        const int2* ep = g_epack[r];
        float4 acc = make_float4(0.f, 0.f, 0.f, 0.f);
        float den = 0.f;
        for (int base = beg; base < end; base += 32) {
            int cnt = end - base; if (cnt > 32) cnt = 32;
            int2 evp = make_int2(0, 0);
            if (lane < cnt) evp = ep[base + lane];
#pragma unroll 4
            for (int j = 0; j < cnt; j++) {
                int s = __shfl_sync(FULL, evp.x, j);
                float ex = __int_as_float(__shfl_sync(FULL, evp.y, j));
                float4 nv = N4[(size_t)s * 32 + lane];
                acc.x += ex * nv.x; acc.y += ex * nv.y;
                acc.z += ex * nv.z; acc.w += ex * nv.w;
                den += ex;
            }
        }
        float iv = (den > 0.f) ? (1.f / den) : 0.f;
        H4[r * 32 + lane] = make_float4(acc.x * iv, acc.y * iv, acc.z * iv, acc.w * iv);
    }
}

// ---------------- K6: attention (warp per 8 nodes; 16B-aligned smem (b,b) staging) ----------------
#define ATTN_WARPS 4
__global__ void __launch_bounds__(128)
k_attn(float* __restrict__ out, int n, const int* __restrict__ tptr) {
    // ulonglong2 elements -> 16-byte alignment guaranteed by type (no casts).
    // bb_sm[w][q][i] covers ht elements 2i and 2i+1 as duplicated (b,b) pairs.
    __shared__ ulonglong2 bb_sm[ATTN_WARPS][8][D / 2];   // 32 KB
    int wlocal = threadIdx.x >> 5;
    int w = (blockIdx.x * blockDim.x + threadIdx.x) >> 5;
    int lane = threadIdx.x & 31;
    int node0 = w * 8;
    if (node0 >= n) return;

    int t = tptr ? tptr[0] : 0;
    t = (t < 0) ? 0 : ((t > 2) ? 2 : t);

    // stage ht for 8 nodes as duplicated (b,b) pairs in smem
#pragma unroll
    for (int q = 0; q < 8; q++) {
        int node = node0 + q;
        float4 x = (node < n)
            ? ((const float4*)(g_h + ((size_t)node * 3 + t) * D))[lane]
            : make_float4(0.f, 0.f, 0.f, 0.f);
        ulonglong2 lo, hi;
        lo.x = pack2(x.x, x.x); lo.y = pack2(x.y, x.y);
        hi.x = pack2(x.z, x.z); hi.y = pack2(x.w, x.w);
        bb_sm[wlocal][q][lane * 2 + 0] = lo;   // elements 4*lane, 4*lane+1
        bb_sm[wlocal][q][lane * 2 + 1] = hi;   // elements 4*lane+2, 4*lane+3
    }
    __syncwarp();

    unsigned long long u01[8], u23[8];
    unsigned long long z = pack2(0.f, 0.f);
#pragma unroll
    for (int q = 0; q < 8; q++) { u01[q] = z; u23[q] = z; }

    const longlong2* M2 = (const longlong2*)g_M;
#pragma unroll 2
    for (int s = 0; s < 32; s++) {
        longlong2 ml0 = M2[(size_t)(s * 4 + 0) * 32 + lane];
        longlong2 ml1 = M2[(size_t)(s * 4 + 1) * 32 + lane];
        longlong2 ml2 = M2[(size_t)(s * 4 + 2) * 32 + lane];
        longlong2 ml3 = M2[(size_t)(s * 4 + 3) * 32 + lane];
#pragma unroll
        for (int q = 0; q < 8; q++) {
            ulonglong2 b01 = bb_sm[wlocal][q][s * 2 + 0];  // (b[4s],b[4s]), (b[4s+1],b[4s+1])
            ulonglong2 b23 = bb_sm[wlocal][q][s * 2 + 1];  // (b[4s+2],..), (b[4s+3],..)
            FMA2(u01[q], (unsigned long long)ml0.x, b01.x, u01[q]);
            FMA2(u23[q], (unsigned long long)ml0.y, b01.x, u23[q]);
            FMA2(u01[q], (unsigned long long)ml1.x, b01.y, u01[q]);
            FMA2(u23[q], (unsigned long long)ml1.y, b01.y, u23[q]);
            FMA2(u01[q], (unsigned long long)ml2.x, b23.x, u01[q]);
            FMA2(u23[q], (unsigned long long)ml2.y, b23.x, u23[q]);
            FMA2(u01[q], (unsigned long long)ml3.x, b23.y, u01[q]);
            FMA2(u23[q], (unsigned long long)ml3.y, b23.y, u23[q]);
        }
    }

    const float sc = 0.0883883476483184f;  // 1/sqrt(128)

#pragma unroll
    for (int q = 0; q < 8; q++) {
        int node = node0 + q;
        if (node >= n) break;
        float2 ua = unpack2(u01[q]);
        float2 ub = unpack2(u23[q]);
        const float4* Hn = (const float4*)(g_h + (size_t)node * 3 * D);
        float4 h0 = Hn[0 * 32 + lane];
        float4 h1 = Hn[1 * 32 + lane];
        float4 h2 = Hn[2 * 32 + lane];
        float e0 = ua.x * h0.x + ua.y * h0.y + ub.x * h0.z + ub.y * h0.w;
        float e1 = ua.x * h1.x + ua.y * h1.y + ub.x * h1.z + ub.y * h1.w;
        float e2 = ua.x * h2.x + ua.y * h2.y + ub.x * h2.z + ub.y * h2.w;
#pragma unroll
        for (int o = 16; o; o >>= 1) {
            e0 += __shfl_xor_sync(FULL, e0, o);
            e1 += __shfl_xor_sync(FULL, e1, o);
            e2 += __shfl_xor_sync(FULL, e2, o);
        }
        e0 *= sc; e1 *= sc; e2 *= sc;
        float mx = fmaxf(e0, fmaxf(e1, e2));
        float a0 = __expf(e0 - mx), a1 = __expf(e1 - mx), a2 = __expf(e2 - mx);
        float is = 1.f / (a0 + a1 + a2);
        a0 *= is; a1 *= is; a2 *= is;

        float4 o4;
        o4.x = a0 * h0.x + a1 * h1.x + a2 * h2.x;
        o4.y = a0 * h0.y + a1 * h1.y + a2 * h2.y;
        o4.z = a0 * h0.z + a1 * h1.z + a2 * h2.z;
        o4.w = a0 * h0.w + a1 * h1.w + a2 * h2.w;
        *(float4*)(out + (size_t)node * D + lane * 4) = o4;
    }
}

// ---------------- launcher ----------------
extern "C" void kernel_launch(void* const* d_in, const int* in_sizes, int n_in,
                              void* d_out, int out_size) {
    const float* Nmat = (const float*)d_in[0];
    const float* W1_0 = (const float*)d_in[1];
    const float* W1_1 = (const float*)d_in[2];
    const float* W1_2 = (const float*)d_in[3];
    const float* w2_0 = (const float*)d_in[4];
    const float* w2_1 = (const float*)d_in[5];
    const float* w2_2 = (const float*)d_in[6];
    const float* Wq   = (const float*)d_in[7];
    const float* Wk   = (const float*)d_in[8];
    const int* s0 = (const int*)d_in[10];
    const int* d0 = (const int*)d_in[11];
    const int* s1 = (const int*)d_in[12];
    const int* d1 = (const int*)d_in[13];
    const int* s2 = (const int*)d_in[14];
    const int* d2 = (const int*)d_in[15];
    const int* tptr = (n_in > 16) ? (const int*)d_in[16] : nullptr;

    int n = in_sizes[0] / D;
    if (n > MAXN) n = MAXN;
    int e0 = in_sizes[10]; if (e0 > MAXE) e0 = MAXE;
    int e1 = in_sizes[12]; if (e1 > MAXE) e1 = MAXE;
    int e2 = in_sizes[14]; if (e2 > MAXE) e2 = MAXE;
    int emax = e0 > e1 ? (e0 > e2 ? e0 : e2) : (e1 > e2 ? e1 : e2);

    // 1: prep (vec | M | zero)
    k_prep<<<134 + 1172, 128>>>(W1_0, W1_1, W1_2, w2_0, w2_1, w2_2, Wq, Wk);

    // 2: scores + counts fused
    int nbs = (n + 7) / 8;
    int ebpr = (emax + 255) / 256;
    k_scores_count<<<nbs + 3 * ebpr, 256>>>(Nmat, n, nbs, ebpr,
                                            d0, d1, d2, e0, e1, e2);
    // 3: scan
    k_scan<<<3, 1024>>>(n);

    // 4: scatter
    dim3 gc(ebpr, 3);
    k_scatter<<<gc, 256>>>(s0, s1, s2, d0, d1, d2, e0, e1, e2);

    // 5: aggregation
    int nb_agg = (n + 7) / 8;
    k_aggA<<<nb_agg, 256>>>(Nmat, n);

    // 6: attention — 128 threads = 4 warps x 8 nodes = 32 nodes per block
    int nb_attn = (n + 31) / 32;
    k_attn<<<nb_attn, 128>>>((float*)d_out, n, tptr);
}

// round 16
// speedup vs baseline: 1.3331x; 1.0381x over previous
#include <cuda_runtime.h>
#include <cstdint>

#define D 128
#define MAXN 100000
#define MAXE 600000
#define NEG_SLOPE 0.01f
#define FULL 0xFFFFFFFFu

// ---------------- scratch (static device globals; no allocation) ----------------
// g_cnt invariant: starts zero (static init); k_prep counts up, k_scatter
// atomicSub's every element back to exactly 0 -> self-restoring across replays.
static __device__ float g_vl[3][D];
static __device__ float g_vr[3][D];
static __device__ float g_M[D * D];                    // Wq^T @ Wk
static __device__ float g_sl[3][MAXN];
static __device__ float g_sr[3][MAXN];
static __device__ int   g_cnt[3][MAXN];                // counts -> consumed as cursors
static __device__ int   g_off[3][MAXN + 1];
static __device__ int2  g_epack[3][MAXE];              // (src, exp-score bits), by dst
static __device__ float g_h[(size_t)MAXN * 3 * D];     // interleaved [node][r][D]

__device__ __forceinline__ unsigned long long pack2(float lo, float hi) {
    unsigned long long r;
    asm("mov.b64 %0, {%1, %2};" : "=l"(r) : "f"(lo), "f"(hi));
    return r;
}
__device__ __forceinline__ float2 unpack2(unsigned long long v) {
    float2 r;
    asm("mov.b64 {%0, %1}, %2;" : "=f"(r.x), "=f"(r.y) : "l"(v));
    return r;
}
#define FMA2(d, a, b, c) \
    asm("fma.rn.f32x2 %0, %1, %2, %3;" : "=l"(d) : "l"(a), "l"(b), "l"(c))

// ---------------- K1: fused prep (vec | M | counts), 128-thread blocks ----------------
// blocks [0,6): v_l/v_r ; [6,134): M ; [134, 134+3*ebpr): in-degree counts
__global__ void k_prep(const float* __restrict__ W1_0, const float* __restrict__ W1_1,
                       const float* __restrict__ W1_2, const float* __restrict__ w2_0,
                       const float* __restrict__ w2_1, const float* __restrict__ w2_2,
                       const float* __restrict__ Wq, const float* __restrict__ Wk,
                       const int* __restrict__ d0, const int* __restrict__ d1,
                       const int* __restrict__ d2, int e0, int e1, int e2, int ebpr) {
    int b = blockIdx.x;
    if (b < 6) {
        int r = b >> 1;
        int half = b & 1;
        const float* W1 = (r == 0) ? W1_0 : (r == 1) ? W1_1 : W1_2;
        const float* w2 = ((r == 0) ? w2_0 : (r == 1) ? w2_1 : w2_2) + half * D;
        int j = threadIdx.x;
        float s = 0.f;
#pragma unroll 8
        for (int i = 0; i < D; i++) s += W1[i * D + j] * w2[i];
        if (half) g_vr[r][j] = s; else g_vl[r][j] = s;
    } else if (b < 134) {
        int dd = b - 6;
        int j = threadIdx.x;
        float s = 0.f;
#pragma unroll 8
        for (int e = 0; e < D; e++) s += Wq[e * D + dd] * Wk[e * D + j];
        g_M[dd * D + j] = s;
    } else {
        int cb = b - 134;
        int r = cb / ebpr;
        int t = (cb - r * ebpr) * 128 + threadIdx.x;
        const int* dst = (r == 0) ? d0 : (r == 1) ? d1 : d2;
        int E = (r == 0) ? e0 : (r == 1) ? e1 : e2;
        if (t >= E) return;
        atomicAdd(&g_cnt[r][dst[t]], 1);
    }
}

// ---------------- K2: fused scores (warp/node) | CSR scan (last 3 blocks) ----------------
__global__ void __launch_bounds__(256)
k_scores_scan(const float* __restrict__ Nmat, int n, int nbs) {
    int b = blockIdx.x;
    if (b < nbs) {
        int w = (b * 256 + threadIdx.x) >> 5;
        int lane = threadIdx.x & 31;
        if (w >= n) return;
        float4 x = ((const float4*)(Nmat + (size_t)w * D))[lane];
        float p0, p1, p2, p3, p4, p5;
        {
            float4 a = ((const float4*)g_vl[0])[lane];
            float4 c = ((const float4*)g_vr[0])[lane];
            p0 = x.x * a.x + x.y * a.y + x.z * a.z + x.w * a.w;
            p1 = x.x * c.x + x.y * c.y + x.z * c.z + x.w * c.w;
        }
        {
            float4 a = ((const float4*)g_vl[1])[lane];
            float4 c = ((const float4*)g_vr[1])[lane];
            p2 = x.x * a.x + x.y * a.y + x.z * a.z + x.w * a.w;
            p3 = x.x * c.x + x.y * c.y + x.z * c.z + x.w * c.w;
        }
        {
            float4 a = ((const float4*)g_vl[2])[lane];
            float4 c = ((const float4*)g_vr[2])[lane];
            p4 = x.x * a.x + x.y * a.y + x.z * a.z + x.w * a.w;
            p5 = x.x * c.x + x.y * c.y + x.z * c.z + x.w * c.w;
        }
#pragma unroll
        for (int o = 16; o; o >>= 1) {
            p0 += __shfl_xor_sync(FULL, p0, o);
            p1 += __shfl_xor_sync(FULL, p1, o);
            p2 += __shfl_xor_sync(FULL, p2, o);
            p3 += __shfl_xor_sync(FULL, p3, o);
            p4 += __shfl_xor_sync(FULL, p4, o);
            p5 += __shfl_xor_sync(FULL, p5, o);
        }
        if (lane == 0) {
            g_sl[0][w] = p0; g_sr[0][w] = p1;
            g_sl[1][w] = p2; g_sr[1][w] = p3;
            g_sl[2][w] = p4; g_sr[2][w] = p5;
        }
    } else {
        // exclusive scan of g_cnt[r] -> g_off[r]; counts were built by k_prep
        int r = b - nbs;
        __shared__ int warpsum[8];
        int tid = threadIdx.x;
        int lane = tid & 31, wid = tid >> 5;
        int chunk = (n + 255) >> 8;
        int beg = tid * chunk;
        int end = beg + chunk; if (end > n) end = n;
        if (beg > n) beg = n;
        int loc = 0;
        for (int i = beg; i < end; i++) loc += g_cnt[r][i];
        int v = loc;
#pragma unroll
        for (int o = 1; o < 32; o <<= 1) {
            int t = __shfl_up_sync(FULL, v, o);
            if (lane >= o) v += t;
        }
        if (lane == 31) warpsum[wid] = v;
        __syncthreads();
        if (wid == 0 && lane < 8) {
            int s = warpsum[lane];
#pragma unroll
            for (int o = 1; o < 8; o <<= 1) {
                int t = __shfl_up_sync(0xFFu, s, o);
                if (lane >= o) s += t;
            }
            warpsum[lane] = s;
        }
        __syncthreads();
        int excl = v - loc + (wid ? warpsum[wid - 1] : 0);
        int run = excl;
        for (int i = beg; i < end; i++) {
            g_off[r][i] = run;
            run += g_cnt[r][i];
        }
        if (end == n) g_off[r][n] = run;
    }
}

// ---------------- K3: scatter edges (counts consumed as cursors -> back to 0) ----------------
__global__ void k_scatter(const int* __restrict__ s0, const int* __restrict__ s1,
                          const int* __restrict__ s2, const int* __restrict__ d0,
                          const int* __restrict__ d1, const int* __restrict__ d2,
                          int e0, int e1, int e2) {
    int r = blockIdx.y;
    const int* src = (r == 0) ? s0 : (r == 1) ? s1 : s2;
    const int* dst = (r == 0) ? d0 : (r == 1) ? d1 : d2;
    int E = (r == 0) ? e0 : (r == 1) ? e1 : e2;
    int t = blockIdx.x * blockDim.x + threadIdx.x;
    if (t >= E) return;
    int s = src[t];
    int d = dst[t];
    float ev = g_sl[r][s] + g_sr[r][d];
    ev = (ev >= 0.f) ? ev : NEG_SLOPE * ev;
    float ex = __expf(ev);
    int pos = g_off[r][d] + atomicSub(&g_cnt[r][d], 1) - 1;
    g_epack[r][pos] = make_int2(s, __float_as_int(ex));
}

// ---------------- K4: aggregation (warp per node) -> interleaved g_h (PROFILED) ----------------
__global__ void __launch_bounds__(256) k_aggA(const float* __restrict__ Nmat, int n) {
    int w = (blockIdx.x * blockDim.x + threadIdx.x) >> 5;
    int lane = threadIdx.x & 31;
    if (w >= n) return;
    const float4* N4 = (const float4*)Nmat;
    float* Hbase = g_h + (size_t)w * 3 * D + lane * 4;
#pragma unroll
    for (int r = 0; r < 3; r++) {
        int beg = g_off[r][w];
        int end = g_off[r][w + 1];
        const int2* ep = g_epack[r];
        float4 acc = make_float4(0.f, 0.f, 0.f, 0.f);
        float den = 0.f;
        for (int base = beg; base < end; base += 32) {
            int cnt = end - base; if (cnt > 32) cnt = 32;
            int2 evp = make_int2(0, 0);
            if (lane < cnt) evp = __ldcs(&ep[base + lane]);   // read-once stream
#pragma unroll 4
            for (int j = 0; j < cnt; j++) {
                int s = __shfl_sync(FULL, evp.x, j);
                float ex = __int_as_float(__shfl_sync(FULL, evp.y, j));
                float4 nv = N4[(size_t)s * 32 + lane];
                acc.x += ex * nv.x; acc.y += ex * nv.y;
                acc.z += ex * nv.z; acc.w += ex * nv.w;
                den += ex;
            }
        }
        float iv = (den > 0.f) ? (1.f / den) : 0.f;
        float4 h4 = make_float4(acc.x * iv, acc.y * iv, acc.z * iv, acc.w * iv);
        __stcs((float4*)(Hbase + r * D), h4);                 // evict-first: keep N in L2
    }
}

// ---------------- K5: attention (warp per 8 nodes; 16B-aligned smem (b,b) staging) ----------------
#define ATTN_WARPS 4
__global__ void __launch_bounds__(128)
k_attn(float* __restrict__ out, int n, const int* __restrict__ tptr) {
    __shared__ ulonglong2 bb_sm[ATTN_WARPS][8][D / 2];   // 32 KB
    int wlocal = threadIdx.x >> 5;
    int w = (blockIdx.x * blockDim.x + threadIdx.x) >> 5;
    int lane = threadIdx.x & 31;
    int node0 = w * 8;
    if (node0 >= n) return;

    int t = tptr ? tptr[0] : 0;
    t = (t < 0) ? 0 : ((t > 2) ? 2 : t);

    // stage ht for 8 nodes as duplicated (b,b) pairs in smem
#pragma unroll
    for (int q = 0; q < 8; q++) {
        int node = node0 + q;
        float4 x = (node < n)
            ? ((const float4*)(g_h + ((size_t)node * 3 + t) * D))[lane]
            : make_float4(0.f, 0.f, 0.f, 0.f);
        ulonglong2 lo, hi;
        lo.x = pack2(x.x, x.x); lo.y = pack2(x.y, x.y);
        hi.x = pack2(x.z, x.z); hi.y = pack2(x.w, x.w);
        bb_sm[wlocal][q][lane * 2 + 0] = lo;
        bb_sm[wlocal][q][lane * 2 + 1] = hi;
    }
    __syncwarp();

    unsigned long long u01[8], u23[8];
    unsigned long long z = pack2(0.f, 0.f);
#pragma unroll
    for (int q = 0; q < 8; q++) { u01[q] = z; u23[q] = z; }

    const longlong2* M2 = (const longlong2*)g_M;
#pragma unroll 2
    for (int s = 0; s < 32; s++) {
        longlong2 ml0 = M2[(size_t)(s * 4 + 0) * 32 + lane];
        longlong2 ml1 = M2[(size_t)(s * 4 + 1) * 32 + lane];
        longlong2 ml2 = M2[(size_t)(s * 4 + 2) * 32 + lane];
        longlong2 ml3 = M2[(size_t)(s * 4 + 3) * 32 + lane];
#pragma unroll
        for (int q = 0; q < 8; q++) {
            ulonglong2 b01 = bb_sm[wlocal][q][s * 2 + 0];
            ulonglong2 b23 = bb_sm[wlocal][q][s * 2 + 1];
            FMA2(u01[q], (unsigned long long)ml0.x, b01.x, u01[q]);
            FMA2(u23[q], (unsigned long long)ml0.y, b01.x, u23[q]);
            FMA2(u01[q], (unsigned long long)ml1.x, b01.y, u01[q]);
            FMA2(u23[q], (unsigned long long)ml1.y, b01.y, u23[q]);
            FMA2(u01[q], (unsigned long long)ml2.x, b23.x, u01[q]);
            FMA2(u23[q], (unsigned long long)ml2.y, b23.x, u23[q]);
            FMA2(u01[q], (unsigned long long)ml3.x, b23.y, u01[q]);
            FMA2(u23[q], (unsigned long long)ml3.y, b23.y, u23[q]);
        }
    }

    const float sc = 0.0883883476483184f;  // 1/sqrt(128)

#pragma unroll
    for (int q = 0; q < 8; q++) {
        int node = node0 + q;
        if (node >= n) break;
        float2 ua = unpack2(u01[q]);
        float2 ub = unpack2(u23[q]);
        const float4* Hn = (const float4*)(g_h + (size_t)node * 3 * D);
        float4 h0 = Hn[0 * 32 + lane];
        float4 h1 = Hn[1 * 32 + lane];
        float4 h2 = Hn[2 * 32 + lane];
        float e0 = ua.x * h0.x + ua.y * h0.y + ub.x * h0.z + ub.y * h0.w;
        float e1 = ua.x * h1.x + ua.y * h1.y + ub.x * h1.z + ub.y * h1.w;
        float e2 = ua.x * h2.x + ua.y * h2.y + ub.x * h2.z + ub.y * h2.w;
#pragma unroll
        for (int o = 16; o; o >>= 1) {
            e0 += __shfl_xor_sync(FULL, e0, o);
            e1 += __shfl_xor_sync(FULL, e1, o);
            e2 += __shfl_xor_sync(FULL, e2, o);
        }
        e0 *= sc; e1 *= sc; e2 *= sc;
        float mx = fmaxf(e0, fmaxf(e1, e2));
        float a0 = __expf(e0 - mx), a1 = __expf(e1 - mx), a2 = __expf(e2 - mx);
        float is = 1.f / (a0 + a1 + a2);
        a0 *= is; a1 *= is; a2 *= is;

        float4 o4;
        o4.x = a0 * h0.x + a1 * h1.x + a2 * h2.x;
        o4.y = a0 * h0.y + a1 * h1.y + a2 * h2.y;
        o4.z = a0 * h0.z + a1 * h1.z + a2 * h2.z;
        o4.w = a0 * h0.w + a1 * h1.w + a2 * h2.w;
        __stcs((float4*)(out + (size_t)node * D + lane * 4), o4);
    }
}

// ---------------- launcher ----------------
extern "C" void kernel_launch(void* const* d_in, const int* in_sizes, int n_in,
                              void* d_out, int out_size) {
    const float* Nmat = (const float*)d_in[0];
    const float* W1_0 = (const float*)d_in[1];
    const float* W1_1 = (const float*)d_in[2];
    const float* W1_2 = (const float*)d_in[3];
    const float* w2_0 = (const float*)d_in[4];
    const float* w2_1 = (const float*)d_in[5];
    const float* w2_2 = (const float*)d_in[6];
    const float* Wq   = (const float*)d_in[7];
    const float* Wk   = (const float*)d_in[8];
    const int* s0 = (const int*)d_in[10];
    const int* d0 = (const int*)d_in[11];
    const int* s1 = (const int*)d_in[12];
    const int* d1 = (const int*)d_in[13];
    const int* s2 = (const int*)d_in[14];
    const int* d2 = (const int*)d_in[15];
    const int* tptr = (n_in > 16) ? (const int*)d_in[16] : nullptr;

    int n = in_sizes[0] / D;
    if (n > MAXN) n = MAXN;
    int e0 = in_sizes[10]; if (e0 > MAXE) e0 = MAXE;
    int e1 = in_sizes[12]; if (e1 > MAXE) e1 = MAXE;
    int e2 = in_sizes[14]; if (e2 > MAXE) e2 = MAXE;
    int emax = e0 > e1 ? (e0 > e2 ? e0 : e2) : (e1 > e2 ? e1 : e2);

    // 1: prep (vec | M | counts)  -- g_cnt enters zero (static init + self-restore)
    int ebpr = (emax + 127) / 128;
    k_prep<<<134 + 3 * ebpr, 128>>>(W1_0, W1_1, W1_2, w2_0, w2_1, w2_2, Wq, Wk,
                                    d0, d1, d2, e0, e1, e2, ebpr);

    // 2: scores | scan
    int nbs = (n + 7) / 8;
    k_scores_scan<<<nbs + 3, 256>>>(Nmat, n, nbs);

    // 3: scatter (restores g_cnt to zero)
    dim3 gc((emax + 255) / 256, 3);
    k_scatter<<<gc, 256>>>(s0, s1, s2, d0, d1, d2, e0, e1, e2);

    // 4: aggregation   (<- profiled slot)
    int nb_agg = (n + 7) / 8;
    k_aggA<<<nb_agg, 256>>>(Nmat, n);

    // 5: attention — 4 warps x 8 nodes = 32 nodes per block
    int nb_attn = (n + 31) / 32;
    k_attn<<<nb_attn, 128>>>((float*)d_out, n, tptr);
}